// round 13
// baseline (speedup 1.0000x reference)
#include <cuda_runtime.h>
#include <math.h>

#define BB 256
#define NT 128
#define TD 64
#define HH 8
#define DH 64
#define IN 512
#define MM 266
#define ES 272
#define FH 256

#define DN    0.35355339059327373f
#define RATIO 0.0613139076f
#define RE    6.13139076e-6f

__device__ float g_q[BB*HH*NT*DH];
__device__ float g_k[BB*HH*NT*DH];
__device__ float g_v[BB*HH*NT*DH];
__device__ float g_Ek[BB*HH*NT*ES];     // [bh][n][m] row-major
__device__ float g_Eq[BB*HH*NT*ES];
__device__ float g_ctxT[BB*HH*DH*ES];
__device__ float g_ksumU[BB*HH*MM];
__device__ float g_vsum[BB*HH*DH];
__device__ float g_qdg[BB*HH*NT];
__device__ float g_Emx[BB*HH*NT];
__device__ float g_csA2[BB*HH*2*DH];
__device__ float g_kss2[BB*HH*2];
__device__ float g_o[BB*NT*IN];
__device__ float g_t[BB*NT*TD];
__device__ float g_ff[BB*NT*FH];
__device__ unsigned g_kmax;

__device__ __forceinline__ unsigned enc_f(float f) {
    unsigned u = __float_as_uint(f);
    return (u & 0x80000000u) ? ~u : (u | 0x80000000u);
}
__device__ __forceinline__ float dec_f(unsigned k) {
    return (k & 0x80000000u) ? __uint_as_float(k & 0x7fffffffu)
                             : __uint_as_float(~k);
}
__device__ __forceinline__ float to_tf32(float x) {
    unsigned r;
    asm("cvt.rna.tf32.f32 %0, %1;" : "=r"(r) : "f"(x));
    return __uint_as_float(r);
}
__device__ __forceinline__ void mma_tf32(float& c0, float& c1, float& c2, float& c3,
                                         unsigned a0, unsigned a1, unsigned a2, unsigned a3,
                                         unsigned b0, unsigned b1)
{
    asm volatile(
        "mma.sync.aligned.m16n8k8.row.col.f32.tf32.tf32.f32 "
        "{%0,%1,%2,%3}, {%4,%5,%6,%7}, {%8,%9}, {%0,%1,%2,%3};"
        : "+f"(c0), "+f"(c1), "+f"(c2), "+f"(c3)
        : "r"(a0), "r"(a1), "r"(a2), "r"(a3), "r"(b0), "r"(b1));
}

__global__ void k_init() { g_kmax = 0u; }

// ---------------- k1_mma: LN1 + one QKV projection ----------------
#define K1_ST 68
#define K1_SMEM ((NT*K1_ST + IN*K1_ST)*4)

__global__ __launch_bounds__(256, 1)
void k1_mma(const float* __restrict__ x,
            const float* __restrict__ g1, const float* __restrict__ b1,
            const float* __restrict__ Wq, const float* __restrict__ bq,
            const float* __restrict__ Wk, const float* __restrict__ bk,
            const float* __restrict__ Wv, const float* __restrict__ bv)
{
    extern __shared__ float sm[];
    float* hs = sm;
    float* Ws = sm + NT*K1_ST;

    int b = blockIdx.x, w = blockIdx.y, t = threadIdx.x;
    int wid = t >> 5, lane = t & 31;
    int g = lane >> 2, q = lane & 3;
    int rA = wid*16 + g, rB = rA + 8;

    const float* W    = (w == 0) ? Wq : (w == 1) ? Wk : Wv;
    const float* bias = (w == 0) ? bq : (w == 1) ? bk : bv;
    float* dst = ((w == 0) ? g_q : (w == 1) ? g_k : g_v) + (size_t)b*HH*NT*DH;

    const float* xb = x + (size_t)b*NT*TD;
    for (int i = t; i < NT*TD; i += 256)
        hs[(i >> 6)*K1_ST + (i & 63)] = xb[i];
    for (int i = t; i < TD*IN; i += 256) {
        int d = i >> 9, j = i & 511;
        Ws[j*K1_ST + d] = to_tf32(W[i]);
    }
    __syncthreads();
    if (t < NT) {
        float* r = &hs[t*K1_ST];
        float mu = 0.f;
#pragma unroll
        for (int d = 0; d < 64; d++) mu += r[d];
        mu *= (1.f/64.f);
        float var = 0.f;
#pragma unroll
        for (int d = 0; d < 64; d++) { float v = r[d]-mu; var += v*v; }
        var *= (1.f/64.f);
        float inv = rsqrtf(var + 1e-5f);
#pragma unroll
        for (int d = 0; d < 64; d++)
            r[d] = to_tf32((r[d]-mu)*inv*g1[d] + b1[d]);
    }
    __syncthreads();

    unsigned a[8][4];
#pragma unroll
    for (int kc = 0; kc < 8; ++kc) {
        a[kc][0] = __float_as_uint(hs[rA*K1_ST + kc*8 + q]);
        a[kc][1] = __float_as_uint(hs[rB*K1_ST + kc*8 + q]);
        a[kc][2] = __float_as_uint(hs[rA*K1_ST + kc*8 + q + 4]);
        a[kc][3] = __float_as_uint(hs[rB*K1_ST + kc*8 + q + 4]);
    }

    for (int nc = 0; nc < 64; ++nc) {
        float c0=0.f, c1=0.f, c2=0.f, c3=0.f;
        const float* pb = Ws + (nc*8 + g)*K1_ST + q;
#pragma unroll
        for (int kc = 0; kc < 8; ++kc) {
            unsigned b0 = __float_as_uint(pb[kc*8]);
            unsigned b1r = __float_as_uint(pb[kc*8 + 4]);
            mma_tf32(c0, c1, c2, c3,
                     a[kc][0], a[kc][1], a[kc][2], a[kc][3], b0, b1r);
        }
        int j0 = nc*8 + 2*q;
        int head = j0 >> 6, doff = j0 & 63;
        float2 bb = *(const float2*)(bias + j0);
        float* dA = dst + ((size_t)head*NT + rA)*DH + doff;
        float* dB = dst + ((size_t)head*NT + rB)*DH + doff;
        *(float2*)dA = make_float2(c0 + bb.x, c1 + bb.y);
        *(float2*)dB = make_float2(c2 + bb.x, c3 + bb.y);
    }
}

// ---------------- kfeat (row-major coalesced Ek/Eq writes) ----------------
#define XS_ST 68
#define PS_ST 68
#define KF_SMEM ((ES*PS_ST + NT*XS_ST)*4)

__global__ __launch_bounds__(256, 2)
void kfeat(const float* __restrict__ proj)
{
    extern __shared__ float dsm[];
    float* Ps = dsm;
    float* Xs = Ps + ES*PS_ST;
    __shared__ float diag[NT];
    __shared__ unsigned s_smax;

    int bh = blockIdx.x, t = threadIdx.x;
    int wid = t >> 5, lane = t & 31;
    int g = lane >> 2, q = lane & 3;
    int r0 = wid*16;
    int rA = r0 + g, rB = r0 + g + 8;

    const float* kg = g_k + (size_t)bh*NT*DH;
    const float* qg = g_q + (size_t)bh*NT*DH;

    if (t == 0) s_smax = 0u;

    for (int i = t; i < ES*DH; i += 256) {
        int m = i >> 6, d = i & 63;
        Ps[m*PS_ST + d] = (m < MM) ? to_tf32(proj[m*64 + d]) : 0.f;
    }
    for (int i = t; i < NT*DH; i += 256) {
        int r = i >> 6, d = i & 63;
        Xs[r*XS_ST + d] = to_tf32(kg[i] * DN);
    }
    if (t < NT) {
        float s = 0.f;
#pragma unroll
        for (int d = 0; d < 64; d++) { float v = kg[t*64+d]*DN; s = fmaf(v,v,s); }
        diag[t] = 0.5f * s;
    }
    __syncthreads();

    // keys -> g_Ek [n][m], coalesced float2
    {
        unsigned a[8][4];
#pragma unroll
        for (int kc = 0; kc < 8; ++kc) {
            a[kc][0] = __float_as_uint(Xs[rA*XS_ST + kc*8 + q]);
            a[kc][1] = __float_as_uint(Xs[rB*XS_ST + kc*8 + q]);
            a[kc][2] = __float_as_uint(Xs[rA*XS_ST + kc*8 + q + 4]);
            a[kc][3] = __float_as_uint(Xs[rB*XS_ST + kc*8 + q + 4]);
        }
        float dgA = diag[rA], dgB = diag[rB];
        float* EA = g_Ek + ((size_t)bh*NT + rA)*ES;
        float* EB = g_Ek + ((size_t)bh*NT + rB)*ES;
        float dmax = -1e30f;

        for (int nc = 0; nc < 34; ++nc) {
            float c0=0.f, c1=0.f, c2=0.f, c3=0.f;
            const float* pb = Ps + (nc*8 + g)*PS_ST + q;
#pragma unroll
            for (int kc = 0; kc < 8; ++kc) {
                unsigned b0 = __float_as_uint(pb[kc*8]);
                unsigned b1 = __float_as_uint(pb[kc*8 + 4]);
                mma_tf32(c0, c1, c2, c3,
                         a[kc][0], a[kc][1], a[kc][2], a[kc][3], b0, b1);
            }
            int n0 = nc*8 + 2*q;
            bool v0 = (n0 < MM), v1 = (n0+1 < MM);
            if (v0) dmax = fmaxf(dmax, fmaxf(c0, c2));
            if (v1) dmax = fmaxf(dmax, fmaxf(c1, c3));
            *(float2*)(EA + n0) = make_float2(__expf(c0 - dgA), __expf(c1 - dgA));
            *(float2*)(EB + n0) = make_float2(__expf(c2 - dgB), __expf(c3 - dgB));
        }
#pragma unroll
        for (int o = 16; o; o >>= 1)
            dmax = fmaxf(dmax, __shfl_xor_sync(0xffffffffu, dmax, o));
        if (lane == 0) atomicMax(&s_smax, enc_f(dmax));
    }
    __syncthreads();
    if (t == 0) atomicMax(&g_kmax, s_smax);

    for (int i = t; i < NT*DH; i += 256) {
        int r = i >> 6, d = i & 63;
        Xs[r*XS_ST + d] = to_tf32(qg[i] * DN);
    }
    if (t < NT) {
        float s = 0.f;
#pragma unroll
        for (int d = 0; d < 64; d++) { float v = qg[t*64+d]*DN; s = fmaf(v,v,s); }
        g_qdg[(size_t)bh*NT + t] = 0.5f * s;
    }
    __syncthreads();

    // queries
    {
        unsigned a[8][4];
#pragma unroll
        for (int kc = 0; kc < 8; ++kc) {
            a[kc][0] = __float_as_uint(Xs[rA*XS_ST + kc*8 + q]);
            a[kc][1] = __float_as_uint(Xs[rB*XS_ST + kc*8 + q]);
            a[kc][2] = __float_as_uint(Xs[rA*XS_ST + kc*8 + q + 4]);
            a[kc][3] = __float_as_uint(Xs[rB*XS_ST + kc*8 + q + 4]);
        }
        float* EA = g_Eq + ((size_t)bh*NT + rA)*ES;
        float* EB = g_Eq + ((size_t)bh*NT + rB)*ES;
        float emxA = 0.f, emxB = 0.f;

        for (int nc = 0; nc < 34; ++nc) {
            float c0=0.f, c1=0.f, c2=0.f, c3=0.f;
            const float* pb = Ps + (nc*8 + g)*PS_ST + q;
#pragma unroll
            for (int kc = 0; kc < 8; ++kc) {
                unsigned b0 = __float_as_uint(pb[kc*8]);
                unsigned b1 = __float_as_uint(pb[kc*8 + 4]);
                mma_tf32(c0, c1, c2, c3,
                         a[kc][0], a[kc][1], a[kc][2], a[kc][3], b0, b1);
            }
            int n0 = nc*8 + 2*q;
            bool v0 = (n0 < MM), v1 = (n0+1 < MM);
            float e0 = __expf(c0), e1 = __expf(c1);
            float e2 = __expf(c2), e3 = __expf(c3);
            if (v0) { emxA = fmaxf(emxA, e0); emxB = fmaxf(emxB, e2); }
            if (v1) { emxA = fmaxf(emxA, e1); emxB = fmaxf(emxB, e3); }
            *(float2*)(EA + n0) = make_float2(e0, e1);
            *(float2*)(EB + n0) = make_float2(e2, e3);
        }
        emxA = fmaxf(emxA, __shfl_xor_sync(0xffffffffu, emxA, 1));
        emxA = fmaxf(emxA, __shfl_xor_sync(0xffffffffu, emxA, 2));
        emxB = fmaxf(emxB, __shfl_xor_sync(0xffffffffu, emxB, 1));
        emxB = fmaxf(emxB, __shfl_xor_sync(0xffffffffu, emxB, 2));
        if (q == 0) {
            g_Emx[(size_t)bh*NT + rA] = emxA;
            g_Emx[(size_t)bh*NT + rB] = emxB;
        }
    }
}

// ---------------- k2b_mma: ctxT = V^T @ Ek, m-split, conflict-free transpose ----------------
#define EKT_ST 73
#define MLOC 136
#define K2B_SMEM ((MLOC*EKT_ST + DH*EKT_ST)*4)   /* 39712+18688 = 58400 */

__global__ __launch_bounds__(256, 3)
void k2b_mma()
{
    extern __shared__ float sm[];
    float* EkTs = sm;               // [136 local m][73] cols = n
    float* Vts  = sm + MLOC*EKT_ST; // [64 d][73]
    __shared__ float csp[2][64];
    __shared__ float redk[8];

    int bh = blockIdx.x, y = blockIdx.y, t = threadIdx.x;
    int mbase = y * MLOC;
    int wid = t >> 5, lane = t & 31;
    int g = lane >> 2, q = lane & 3;
    int mtile = wid >> 1;
    int w2 = wid & 1;
    int ntb = w2 ? 9 : 0;
    int ntc = w2 ? 8 : 9;

    const float* Ekg = g_Ek + (size_t)bh*NT*ES + mbase;
    const float* vg  = g_v  + (size_t)bh*NT*DH;

    float acc[9][4];
#pragma unroll
    for (int j = 0; j < 9; ++j) { acc[j][0]=0.f; acc[j][1]=0.f; acc[j][2]=0.f; acc[j][3]=0.f; }
    float ks0 = 0.f, vs_r = 0.f;
    int dA = mtile*16 + g, dB = dA + 8;

    for (int c = 0; c < 2; ++c) {
        int n0 = c*64;
        for (int i = t; i < 64*64; i += 256) {
            int n = i >> 6, d = i & 63;
            Vts[d*EKT_ST + n] = vg[(n0+n)*64 + d];
        }
        for (int i = t; i < 64*MLOC; i += 256) {
            int n = i / MLOC, m = i - n*MLOC;
            EkTs[m*EKT_ST + n] = Ekg[(size_t)(n0+n)*ES + m];
        }
        __syncthreads();

        if (t < MLOC) {
            float s = 0.f;
            const float* r1 = EkTs + t*EKT_ST;
#pragma unroll
            for (int j = 0; j < 64; ++j) s += r1[j];
            ks0 += s;
        }
        if (t < 64) {
            float sv = 0.f;
            const float* rv = Vts + t*EKT_ST;
#pragma unroll
            for (int j = 0; j < 64; ++j) sv += rv[j];
            vs_r += sv;
        }

#pragma unroll
        for (int ks = 0; ks < 8; ++ks) {
            unsigned a0 = __float_as_uint(Vts[dA*EKT_ST + ks*8 + q]);
            unsigned a1 = __float_as_uint(Vts[dB*EKT_ST + ks*8 + q]);
            unsigned a2 = __float_as_uint(Vts[dA*EKT_ST + ks*8 + q + 4]);
            unsigned a3 = __float_as_uint(Vts[dB*EKT_ST + ks*8 + q + 4]);
#pragma unroll
            for (int j = 0; j < 9; ++j) {
                if (j < ntc) {
                    int mrow = (ntb + j)*8 + g;
                    unsigned b0 = __float_as_uint(EkTs[mrow*EKT_ST + ks*8 + q]);
                    unsigned b1 = __float_as_uint(EkTs[mrow*EKT_ST + ks*8 + q + 4]);
                    mma_tf32(acc[j][0], acc[j][1], acc[j][2], acc[j][3],
                             a0, a1, a2, a3, b0, b1);
                }
            }
        }
        __syncthreads();
    }

    // csA partials from live accumulators
    {
        float pA = 0.f, pB = 0.f;
#pragma unroll
        for (int j = 0; j < 9; ++j) {
            if (j < ntc) {
                int m0 = mbase + (ntb + j)*8 + 2*q;
                if (m0   < MM) { pA += acc[j][0]; pB += acc[j][2]; }
                if (m0+1 < MM) { pA += acc[j][1]; pB += acc[j][3]; }
            }
        }
        pA += __shfl_xor_sync(0xffffffffu, pA, 1);
        pA += __shfl_xor_sync(0xffffffffu, pA, 2);
        pB += __shfl_xor_sync(0xffffffffu, pB, 1);
        pB += __shfl_xor_sync(0xffffffffu, pB, 2);
        if (q == 0) { csp[w2][dA] = pA; csp[w2][dB] = pB; }
    }

    // kss partial
    {
        float kt = (t < MLOC && mbase + t < MM) ? ks0 : 0.f;
#pragma unroll
        for (int o = 16; o; o >>= 1) kt += __shfl_xor_sync(0xffffffffu, kt, o);
        if (lane == 0) redk[wid] = kt;
    }

    float* ctA = g_ctxT + ((size_t)bh*DH + dA)*ES;
    float* ctB = g_ctxT + ((size_t)bh*DH + dB)*ES;
#pragma unroll
    for (int j = 0; j < 9; ++j) {
        if (j < ntc) {
            int m0 = mbase + (ntb + j)*8 + 2*q;
            float e0 = (m0   < MM) ? acc[j][0] : 0.f;
            float e1 = (m0+1 < MM) ? acc[j][1] : 0.f;
            float e2 = (m0   < MM) ? acc[j][2] : 0.f;
            float e3 = (m0+1 < MM) ? acc[j][3] : 0.f;
            *(float2*)(ctA + m0) = make_float2(e0, e1);
            *(float2*)(ctB + m0) = make_float2(e2, e3);
        }
    }
    if (t < MLOC && mbase + t < MM) g_ksumU[(size_t)bh*MM + mbase + t] = ks0;
    __syncthreads();
    if (t < DH) {
        if (y == 0) g_vsum[(size_t)bh*DH + t] = vs_r;
        g_csA2[((size_t)bh*2 + y)*DH + t] = csp[0][t] + csp[1][t];
    }
    if (t == 0) {
        float s = 0.f;
#pragma unroll
        for (int w = 0; w < 8; ++w) s += redk[w];
        g_kss2[(size_t)bh*2 + y] = s;
    }
}

// ---------------- k3b_mma: O = Eq @ ctx_scaled, Tn inline ----------------
#define EQ_ST 137
#define K3B_SMEM ((NT*EQ_ST + DH*EQ_ST)*4)

__global__ __launch_bounds__(512, 1)
void k3b_mma()
{
    extern __shared__ float sm[];
    float* Eqs   = sm;
    float* ctxTs = sm + NT*EQ_ST;
    __shared__ float qd_s[NT], Emx_s[NT], Tn_s[NT], cs_s[DH], vs_s[DH];
    __shared__ float ksm_s[ES];
    __shared__ float skss;

    int bh = blockIdx.x, t = threadIdx.x;
    int wid = t >> 5, lane = t & 31;
    int g = lane >> 2, q = lane & 3;
    int mtile = wid >> 1;
    int dbase = (wid & 1)*32;

    float A = RATIO * __expf(-dec_f(g_kmax));
    if (t == 0)
        skss = fmaf(A, g_kss2[(size_t)bh*2] + g_kss2[(size_t)bh*2 + 1],
                    (float)MM * RE * 128.f);
    if (t < NT) {
        qd_s[t]  = g_qdg[(size_t)bh*NT + t];
        Emx_s[t] = g_Emx[(size_t)bh*NT + t];
        Tn_s[t]  = 0.f;
    }
    if (t < DH) {
        float vs = g_vsum[(size_t)bh*DH + t];
        vs_s[t] = vs;
        cs_s[t] = fmaf(A, g_csA2[(size_t)bh*2*DH + t] + g_csA2[((size_t)bh*2+1)*DH + t],
                       (float)MM * RE * vs);
    }
    __syncthreads();
    for (int i = t; i < ES; i += 512)
        ksm_s[i] = (i < MM) ? fmaf(A, g_ksumU[(size_t)bh*MM + i], RE*128.f) : 0.f;

    const float* Eqg = g_Eq + (size_t)bh*NT*ES;
    const float* ctg = g_ctxT + (size_t)bh*DH*ES;

    float acc[4][4];
#pragma unroll
    for (int j = 0; j < 4; ++j) { acc[j][0]=0.f; acc[j][1]=0.f; acc[j][2]=0.f; acc[j][3]=0.f; }

    for (int c = 0; c < 2; ++c) {
        int m0 = c*136;
        for (int i = t; i < NT*136; i += 512) {
            int r = i / 136, cc = i - r*136;
            Eqs[r*EQ_ST + cc] = Eqg[(size_t)r*ES + m0 + cc];
        }
        for (int i = t; i < DH*136; i += 512) {
            int d = i / 136, cc = i - d*136;
            int mg = m0 + cc;
            float raw = ctg[(size_t)d*ES + mg];
            ctxTs[d*EQ_ST + cc] = (mg < MM) ? fmaf(A, raw, RE*vs_s[d]) : 0.f;
        }
        __syncthreads();

        for (int j = 0; j < 8; ++j) {
            int n = wid*8 + j;
            const float* er = Eqs + n*EQ_ST;
            float s = 0.f;
            for (int cc = lane; cc < 136; cc += 32)
                s = fmaf(er[cc], ksm_s[m0 + cc], s);
#pragma unroll
            for (int o = 16; o; o >>= 1) s += __shfl_xor_sync(0xffffffffu, s, o);
            if (lane == 0) Tn_s[n] += s;
        }

#pragma unroll
        for (int ks = 0; ks < 17; ++ks) {
            unsigned a0 = __float_as_uint(Eqs[(mtile*16+g)*EQ_ST + ks*8 + q]);
            unsigned a1 = __float_as_uint(Eqs[(mtile*16+g+8)*EQ_ST + ks*8 + q]);
            unsigned a2 = __float_as_uint(Eqs[(mtile*16+g)*EQ_ST + ks*8 + q + 4]);
            unsigned a3 = __float_as_uint(Eqs[(mtile*16+g+8)*EQ_ST + ks*8 + q + 4]);
#pragma unroll
            for (int nt = 0; nt < 4; ++nt) {
                int drow = dbase + nt*8 + g;
                unsigned b0 = __float_as_uint(ctxTs[drow*EQ_ST + ks*8 + q]);
                unsigned b1 = __float_as_uint(ctxTs[drow*EQ_ST + ks*8 + q + 4]);
                mma_tf32(acc[nt][0], acc[nt][1], acc[nt][2], acc[nt][3],
                         a0, a1, a2, a3, b0, b1);
            }
        }
        __syncthreads();
    }

    int rA = mtile*16 + g, rB = rA + 8;
    float rqA = RATIO * __expf(-qd_s[rA]) / Emx_s[rA];
    float rqB = RATIO * __expf(-qd_s[rB]) / Emx_s[rB];
    float kss = skss;
    float invA = 1.0f / fmaf(rqA, Tn_s[rA], RE*kss);
    float invB = 1.0f / fmaf(rqB, Tn_s[rB], RE*kss);
    int b = bh >> 3, h = bh & 7;
    float* oA = g_o + ((size_t)(b*NT + rA))*IN + h*DH;
    float* oB = g_o + ((size_t)(b*NT + rB))*IN + h*DH;
#pragma unroll
    for (int nt = 0; nt < 4; ++nt) {
        int d = dbase + nt*8 + 2*q;
        float2 vA, vB;
        vA.x = fmaf(rqA, acc[nt][0], RE*cs_s[d  ])*invA;
        vA.y = fmaf(rqA, acc[nt][1], RE*cs_s[d+1])*invA;
        vB.x = fmaf(rqB, acc[nt][2], RE*cs_s[d  ])*invB;
        vB.y = fmaf(rqB, acc[nt][3], RE*cs_s[d+1])*invB;
        *(float2*)(oA + d) = vA;
        *(float2*)(oB + d) = vB;
    }
}

// ---------------- k4a_mma ----------------
#define K4A_ST 132
#define K4A_SMEM ((NT*K4A_ST + DH*K4A_ST)*4)

__global__ __launch_bounds__(256, 2)
void k4a_mma(const float* __restrict__ x,
             const float* __restrict__ Wo, const float* __restrict__ bo)
{
    extern __shared__ float sm[];
    float* Os = sm;
    float* Ws = sm + NT*K4A_ST;

    int b = blockIdx.x, t = threadIdx.x;
    int wid = t >> 5, lane = t & 31;
    int g = lane >> 2, q = lane & 3;
    int rA = wid*16 + g, rB = rA + 8;

    float acc[8][4];
#pragma unroll
    for (int j = 0; j < 8; ++j) { acc[j][0]=0.f; acc[j][1]=0.f; acc[j][2]=0.f; acc[j][3]=0.f; }

    const float* ob = g_o + (size_t)b*NT*IN;

    for (int c = 0; c < 4; ++c) {
        int k0 = c*128;
        for (int i = t; i < NT*128; i += 256) {
            int r = i >> 7, kc = i & 127;
            Os[r*K4A_ST + kc] = to_tf32(ob[(size_t)r*IN + k0 + kc]);
        }
        for (int i = t; i < DH*128; i += 256) {
            int k = i >> 6, d = i & 63;
            Ws[d*K4A_ST + k] = to_tf32(Wo[(size_t)(k0+k)*TD + d]);
        }
        __syncthreads();

#pragma unroll
        for (int ks = 0; ks < 16; ++ks) {
            unsigned a0 = __float_as_uint(Os[rA*K4A_ST + ks*8 + q]);
            unsigned a1 = __float_as_uint(Os[rB*K4A_ST + ks*8 + q]);
            unsigned a2 = __float_as_uint(Os[rA*K4A_ST + ks*8 + q + 4]);
            unsigned a3 = __float_as_uint(Os[rB*K4A_ST + ks*8 + q + 4]);
#pragma unroll
            for (int nt = 0; nt < 8; ++nt) {
                int drow = nt*8 + g;
                unsigned b0 = __float_as_uint(Ws[drow*K4A_ST + ks*8 + q]);
                unsigned b1 = __float_as_uint(Ws[drow*K4A_ST + ks*8 + q + 4]);
                mma_tf32(acc[nt][0], acc[nt][1], acc[nt][2], acc[nt][3],
                         a0, a1, a2, a3, b0, b1);
            }
        }
        __syncthreads();
    }

    const float* xb = x + (size_t)b*NT*TD;
    float* tb = g_t + (size_t)b*NT*TD;
#pragma unroll
    for (int nt = 0; nt < 8; ++nt) {
        int d = nt*8 + 2*q;
        float2 bb = *(const float2*)(bo + d);
        float2 xA = *(const float2*)(xb + rA*TD + d);
        float2 xB = *(const float2*)(xb + rB*TD + d);
        *(float2*)(tb + rA*TD + d) =
            make_float2(acc[nt][0] + bb.x + xA.x, acc[nt][1] + bb.y + xA.y);
        *(float2*)(tb + rB*TD + d) =
            make_float2(acc[nt][2] + bb.x + xB.x, acc[nt][3] + bb.y + xB.y);
    }
}

// ---------------- k4b1: LN2 + FF1 (mma) + GELU -> g_ff ----------------
#define FF1_ST 68
#define K4B1_SMEM ((NT*FF1_ST + FH*FF1_ST)*4)

__global__ __launch_bounds__(256, 2)
void k4b1(const float* __restrict__ g2, const float* __restrict__ b2,
          const float* __restrict__ W1, const float* __restrict__ c1)
{
    extern __shared__ float sm[];
    float* hs = sm;
    float* Ws = sm + NT*FF1_ST;

    int b = blockIdx.x, t = threadIdx.x;
    int wid = t >> 5, lane = t & 31;
    int g = lane >> 2, q = lane & 3;
    int rA = wid*16 + g, rB = rA + 8;

    for (int i = t; i < TD*FH; i += 256) {
        int d = i >> 8, j = i & 255;
        Ws[j*FF1_ST + d] = to_tf32(W1[i]);
    }
    if (t < NT) {
        const float* tr = g_t + ((size_t)(b*NT + t))*TD;
        float tv[64];
#pragma unroll
        for (int j = 0; j < 16; ++j) {
            float4 t4 = *(const float4*)(tr + 4*j);
            tv[4*j]=t4.x; tv[4*j+1]=t4.y; tv[4*j+2]=t4.z; tv[4*j+3]=t4.w;
        }
        float mu = 0.f;
#pragma unroll
        for (int d = 0; d < 64; d++) mu += tv[d];
        mu *= (1.f/64.f);
        float var = 0.f;
#pragma unroll
        for (int d = 0; d < 64; d++) { float v = tv[d]-mu; var += v*v; }
        var *= (1.f/64.f);
        float inv = rsqrtf(var + 1e-5f);
#pragma unroll
        for (int d = 0; d < 64; d++)
            hs[t*FF1_ST + d] = to_tf32((tv[d]-mu)*inv*g2[d] + b2[d]);
    }
    __syncthreads();

    unsigned a[8][4];
#pragma unroll
    for (int kc = 0; kc < 8; ++kc) {
        a[kc][0] = __float_as_uint(hs[rA*FF1_ST + kc*8 + q]);
        a[kc][1] = __float_as_uint(hs[rB*FF1_ST + kc*8 + q]);
        a[kc][2] = __float_as_uint(hs[rA*FF1_ST + kc*8 + q + 4]);
        a[kc][3] = __float_as_uint(hs[rB*FF1_ST + kc*8 + q + 4]);
    }

    float* ffb = g_ff + (size_t)b*NT*FH;
    for (int nc = 0; nc < 32; ++nc) {
        float c0=0.f, c1r=0.f, c2=0.f, c3=0.f;
        const float* pb = Ws + (nc*8 + g)*FF1_ST + q;
#pragma unroll
        for (int kc = 0; kc < 8; ++kc) {
            unsigned b0 = __float_as_uint(pb[kc*8]);
            unsigned b1 = __float_as_uint(pb[kc*8 + 4]);
            mma_tf32(c0, c1r, c2, c3,
                     a[kc][0], a[kc][1], a[kc][2], a[kc][3], b0, b1);
        }
        int j0 = nc*8 + 2*q;
        float2 cc = *(const float2*)(c1 + j0);
        float v0 = c0 + cc.x, v1 = c1r + cc.y, v2 = c2 + cc.x, v3 = c3 + cc.y;
        v0 = 0.5f*v0*(1.f + erff(v0*0.70710678f));
        v1 = 0.5f*v1*(1.f + erff(v1*0.70710678f));
        v2 = 0.5f*v2*(1.f + erff(v2*0.70710678f));
        v3 = 0.5f*v3*(1.f + erff(v3*0.70710678f));
        *(float2*)(ffb + (size_t)rA*FH + j0) = make_float2(v0, v1);
        *(float2*)(ffb + (size_t)rB*FH + j0) = make_float2(v2, v3);
    }
}

// ---------------- k4b2: FF2 (mma) + residual + LN3 + pool + head ----------------
#define FF2_ST 132
#define K4B2_SMEM ((NT*FF2_ST + DH*FF2_ST + NT*65)*4)

__global__ __launch_bounds__(256, 1)
void k4b2(const float* __restrict__ x,
          const float* __restrict__ W2, const float* __restrict__ c2,
          const float* __restrict__ g3, const float* __restrict__ b3,
          const float* __restrict__ Wf1, const float* __restrict__ bf1,
          const float* __restrict__ Wf2, const float* __restrict__ bf2,
          float* __restrict__ out)
{
    extern __shared__ float sm[];
    float* As = sm;
    float* Ws = sm + NT*FF2_ST;
    float* rs = Ws + DH*FF2_ST;
    __shared__ float psm[64];
    __shared__ float red[8];

    int b = blockIdx.x, t = threadIdx.x;
    int wid = t >> 5, lane = t & 31;
    int g = lane >> 2, q = lane & 3;
    int rA = wid*16 + g, rB = rA + 8;

    float acc[8][4];
#pragma unroll
    for (int j = 0; j < 8; ++j) { acc[j][0]=0.f; acc[j][1]=0.f; acc[j][2]=0.f; acc[j][3]=0.f; }

    const float* ffb = g_ff + (size_t)b*NT*FH;

    for (int c = 0; c < 2; ++c) {
        int k0 = c*128;
        for (int i = t; i < NT*128; i += 256) {
            int r = i >> 7, kc = i & 127;
            As[r*FF2_ST + kc] = to_tf32(ffb[(size_t)r*FH + k0 + kc]);
        }
        for (int i = t; i < DH*128; i += 256) {
            int kc = i >> 6, d = i & 63;
            Ws[d*FF2_ST + kc] = to_tf32(W2[(size_t)(k0+kc)*TD + d]);
        }
        __syncthreads();

#pragma unroll
        for (int ks = 0; ks < 16; ++ks) {
            unsigned a0 = __float_as_uint(As[rA*FF2_ST + ks*8 + q]);
            unsigned a1 = __float_as_uint(As[rB*FF2_ST + ks*8 + q]);
            unsigned a2 = __float_as_uint(As[rA*FF2_ST + ks*8 + q + 4]);
            unsigned a3 = __float_as_uint(As[rB*FF2_ST + ks*8 + q + 4]);
#pragma unroll
            for (int nt = 0; nt < 8; ++nt) {
                int drow = nt*8 + g;
                unsigned b0 = __float_as_uint(Ws[drow*FF2_ST + ks*8 + q]);
                unsigned b1 = __float_as_uint(Ws[drow*FF2_ST + ks*8 + q + 4]);
                mma_tf32(acc[nt][0], acc[nt][1], acc[nt][2], acc[nt][3],
                         a0, a1, a2, a3, b0, b1);
            }
        }
        __syncthreads();
    }

    const float* xb = x + (size_t)b*NT*TD;
    const float* tb = g_t + (size_t)b*NT*TD;
#pragma unroll
    for (int nt = 0; nt < 8; ++nt) {
        int d = nt*8 + 2*q;
        float2 cc = *(const float2*)(c2 + d);
        float2 tA = *(const float2*)(tb + rA*TD + d);
        float2 tB = *(const float2*)(tb + rB*TD + d);
        float2 xA = *(const float2*)(xb + rA*TD + d);
        float2 xB = *(const float2*)(xb + rB*TD + d);
        rs[rA*65 + d]     = acc[nt][0] + cc.x + tA.x + xA.x;
        rs[rA*65 + d + 1] = acc[nt][1] + cc.y + tA.y + xA.y;
        rs[rB*65 + d]     = acc[nt][2] + cc.x + tB.x + xB.x;
        rs[rB*65 + d + 1] = acc[nt][3] + cc.y + tB.y + xB.y;
    }
    __syncthreads();

    if (t < NT) {
        float* r = &rs[t*65];
        float mu = 0.f;
#pragma unroll
        for (int d = 0; d < 64; d++) mu += r[d];
        mu *= (1.f/64.f);
        float var = 0.f;
#pragma unroll
        for (int d = 0; d < 64; d++) { float v = r[d]-mu; var += v*v; }
        var *= (1.f/64.f);
        float inv = rsqrtf(var + 1e-5f);
#pragma unroll
        for (int d = 0; d < 64; d++)
            r[d] = (r[d]-mu)*inv*g3[d] + b3[d];
    }
    __syncthreads();

    if (t < TD) {
        float s = 0.f;
        for (int nn = 0; nn < NT; ++nn) s += rs[nn*65 + t];
        psm[t] = s * (1.f/128.f);
    }
    __syncthreads();

    float val = 0.f;
    if (t < 128) {
        float s = bf1[t];
        for (int d = 0; d < TD; ++d)
            s = fmaf(psm[d], Wf1[d*128 + t], s);
        s = fmaxf(s, 0.f);
        val = s * Wf2[t];
    }
#pragma unroll
    for (int o = 16; o; o >>= 1)
        val += __shfl_xor_sync(0xffffffffu, val, o);
    if ((t & 31) == 0) red[t >> 5] = val;
    __syncthreads();
    if (t == 0)
        out[b] = red[0] + red[1] + red[2] + red[3] + bf2[0];
}

// ---------------- launch ----------------
extern "C" void kernel_launch(void* const* d_in, const int* in_sizes, int n_in,
                              void* d_out, int out_size) {
    const float* x    = (const float*)d_in[0];
    const float* g1   = (const float*)d_in[1];
    const float* b1   = (const float*)d_in[2];
    const float* Wq   = (const float*)d_in[3];
    const float* bq   = (const float*)d_in[4];
    const float* Wk   = (const float*)d_in[5];
    const float* bk   = (const float*)d_in[6];
    const float* Wv   = (const float*)d_in[7];
    const float* bv   = (const float*)d_in[8];
    const float* Wo   = (const float*)d_in[9];
    const float* bo   = (const float*)d_in[10];
    const float* proj = (const float*)d_in[11];
    const float* g2   = (const float*)d_in[12];
    const float* b2   = (const float*)d_in[13];
    const float* W1   = (const float*)d_in[14];
    const float* c1   = (const float*)d_in[15];
    const float* W2   = (const float*)d_in[16];
    const float* c2   = (const float*)d_in[17];
    const float* g3   = (const float*)d_in[18];
    const float* b3   = (const float*)d_in[19];
    const float* Wf1  = (const float*)d_in[20];
    const float* bf1  = (const float*)d_in[21];
    const float* Wf2  = (const float*)d_in[22];
    const float* bf2  = (const float*)d_in[23];
    float* out = (float*)d_out;

    cudaFuncSetAttribute(k1_mma,  cudaFuncAttributeMaxDynamicSharedMemorySize, K1_SMEM);
    cudaFuncSetAttribute(kfeat,   cudaFuncAttributeMaxDynamicSharedMemorySize, KF_SMEM);
    cudaFuncSetAttribute(k2b_mma, cudaFuncAttributeMaxDynamicSharedMemorySize, K2B_SMEM);
    cudaFuncSetAttribute(k3b_mma, cudaFuncAttributeMaxDynamicSharedMemorySize, K3B_SMEM);
    cudaFuncSetAttribute(k4a_mma, cudaFuncAttributeMaxDynamicSharedMemorySize, K4A_SMEM);
    cudaFuncSetAttribute(k4b1,    cudaFuncAttributeMaxDynamicSharedMemorySize, K4B1_SMEM);
    cudaFuncSetAttribute(k4b2,    cudaFuncAttributeMaxDynamicSharedMemorySize, K4B2_SMEM);

    k_init<<<1, 1>>>();
    k1_mma<<<dim3(BB, 3), 256, K1_SMEM>>>(x, g1, b1, Wq, bq, Wk, bk, Wv, bv);
    kfeat<<<BB*HH, 256, KF_SMEM>>>(proj);
    k2b_mma<<<dim3(BB*HH, 2), 256, K2B_SMEM>>>();
    k3b_mma<<<BB*HH, 512, K3B_SMEM>>>();
    k4a_mma<<<BB, 256, K4A_SMEM>>>(x, Wo, bo);
    k4b1<<<BB, 256, K4B1_SMEM>>>(g2, b2, W1, c1);
    k4b2<<<BB, 256, K4B2_SMEM>>>(x, W2, c2, g3, b3, Wf1, bf1, Wf2, bf2, out);
}

// round 14
// speedup vs baseline: 1.0441x; 1.0441x over previous
#include <cuda_runtime.h>
#include <math.h>

#define BB 256
#define NT 128
#define TD 64
#define HH 8
#define DH 64
#define IN 512
#define MM 266
#define ES 272
#define FH 256

#define DN    0.35355339059327373f
#define RATIO 0.0613139076f
#define RE    6.13139076e-6f

__device__ float g_q[BB*HH*NT*DH];
__device__ float g_k[BB*HH*NT*DH];
__device__ float g_v[BB*HH*NT*DH];
__device__ float g_Ek[BB*HH*NT*ES];
__device__ float g_Eq[BB*HH*NT*ES];
__device__ float g_ctxT[BB*HH*DH*ES];
__device__ float g_ksumU[BB*HH*MM];
__device__ float g_vsum[BB*HH*DH];
__device__ float g_qdg[BB*HH*NT];
__device__ float g_Emx[BB*HH*NT];
__device__ float g_csA[BB*HH*DH];
__device__ float g_kss[BB*HH];
__device__ float g_o[BB*NT*IN];
__device__ float g_t[BB*NT*TD];
__device__ float g_ff[BB*NT*FH];
__device__ unsigned g_kmax;

__device__ __forceinline__ unsigned enc_f(float f) {
    unsigned u = __float_as_uint(f);
    return (u & 0x80000000u) ? ~u : (u | 0x80000000u);
}
__device__ __forceinline__ float dec_f(unsigned k) {
    return (k & 0x80000000u) ? __uint_as_float(k & 0x7fffffffu)
                             : __uint_as_float(~k);
}
__device__ __forceinline__ float to_tf32(float x) {
    unsigned r;
    asm("cvt.rna.tf32.f32 %0, %1;" : "=r"(r) : "f"(x));
    return __uint_as_float(r);
}
__device__ __forceinline__ void mma_tf32(float& c0, float& c1, float& c2, float& c3,
                                         unsigned a0, unsigned a1, unsigned a2, unsigned a3,
                                         unsigned b0, unsigned b1)
{
    asm volatile(
        "mma.sync.aligned.m16n8k8.row.col.f32.tf32.tf32.f32 "
        "{%0,%1,%2,%3}, {%4,%5,%6,%7}, {%8,%9}, {%0,%1,%2,%3};"
        : "+f"(c0), "+f"(c1), "+f"(c2), "+f"(c3)
        : "r"(a0), "r"(a1), "r"(a2), "r"(a3), "r"(b0), "r"(b1));
}

__global__ void k_init() { g_kmax = 0u; }

// ---------------- k1_mma: LN1 + half of one QKV projection (grid.z=2) ----------------
#define K1_ST 68
#define K1_SMEM ((NT*K1_ST + 256*K1_ST)*4)   /* 34816 + 69632 = 104448 */

__global__ __launch_bounds__(256, 2)
void k1_mma(const float* __restrict__ x,
            const float* __restrict__ g1, const float* __restrict__ b1,
            const float* __restrict__ Wq, const float* __restrict__ bq,
            const float* __restrict__ Wk, const float* __restrict__ bk,
            const float* __restrict__ Wv, const float* __restrict__ bv)
{
    extern __shared__ float sm[];
    float* hs = sm;                 // [128][68]
    float* Ws = sm + NT*K1_ST;      // [256 j][68]

    int b = blockIdx.x, w = blockIdx.y, t = threadIdx.x;
    int jbase = blockIdx.z * 256;
    int wid = t >> 5, lane = t & 31;
    int g = lane >> 2, q = lane & 3;
    int rA = wid*16 + g, rB = rA + 8;

    const float* W    = (w == 0) ? Wq : (w == 1) ? Wk : Wv;
    const float* bias = (w == 0) ? bq : (w == 1) ? bk : bv;
    float* dst = ((w == 0) ? g_q : (w == 1) ? g_k : g_v) + (size_t)b*HH*NT*DH;

    const float* xb = x + (size_t)b*NT*TD;
    for (int i = t; i < NT*TD; i += 256)
        hs[(i >> 6)*K1_ST + (i & 63)] = xb[i];
    for (int i = t; i < TD*256; i += 256) {
        int d = i >> 8, j = i & 255;
        Ws[j*K1_ST + d] = to_tf32(W[d*IN + jbase + j]);
    }
    __syncthreads();
    if (t < NT) {
        float* r = &hs[t*K1_ST];
        float mu = 0.f;
#pragma unroll
        for (int d = 0; d < 64; d++) mu += r[d];
        mu *= (1.f/64.f);
        float var = 0.f;
#pragma unroll
        for (int d = 0; d < 64; d++) { float v = r[d]-mu; var += v*v; }
        var *= (1.f/64.f);
        float inv = rsqrtf(var + 1e-5f);
#pragma unroll
        for (int d = 0; d < 64; d++)
            r[d] = to_tf32((r[d]-mu)*inv*g1[d] + b1[d]);
    }
    __syncthreads();

    unsigned a[8][4];
#pragma unroll
    for (int kc = 0; kc < 8; ++kc) {
        a[kc][0] = __float_as_uint(hs[rA*K1_ST + kc*8 + q]);
        a[kc][1] = __float_as_uint(hs[rB*K1_ST + kc*8 + q]);
        a[kc][2] = __float_as_uint(hs[rA*K1_ST + kc*8 + q + 4]);
        a[kc][3] = __float_as_uint(hs[rB*K1_ST + kc*8 + q + 4]);
    }

    for (int nc = 0; nc < 32; ++nc) {
        float c0=0.f, c1=0.f, c2=0.f, c3=0.f;
        const float* pb = Ws + (nc*8 + g)*K1_ST + q;
#pragma unroll
        for (int kc = 0; kc < 8; ++kc) {
            unsigned b0 = __float_as_uint(pb[kc*8]);
            unsigned b1r = __float_as_uint(pb[kc*8 + 4]);
            mma_tf32(c0, c1, c2, c3,
                     a[kc][0], a[kc][1], a[kc][2], a[kc][3], b0, b1r);
        }
        int j0 = jbase + nc*8 + 2*q;
        int head = j0 >> 6, doff = j0 & 63;
        float2 bb = *(const float2*)(bias + j0);
        float* dA = dst + ((size_t)head*NT + rA)*DH + doff;
        float* dB = dst + ((size_t)head*NT + rB)*DH + doff;
        *(float2*)dA = make_float2(c0 + bb.x, c1 + bb.y);
        *(float2*)dB = make_float2(c2 + bb.x, c3 + bb.y);
    }
}

// ---------------- kfeat (row-major coalesced Ek/Eq writes) ----------------
#define XS_ST 68
#define PS_ST 68
#define KF_SMEM ((ES*PS_ST + NT*XS_ST)*4)

__global__ __launch_bounds__(256, 2)
void kfeat(const float* __restrict__ proj)
{
    extern __shared__ float dsm[];
    float* Ps = dsm;
    float* Xs = Ps + ES*PS_ST;
    __shared__ float diag[NT];
    __shared__ unsigned s_smax;

    int bh = blockIdx.x, t = threadIdx.x;
    int wid = t >> 5, lane = t & 31;
    int g = lane >> 2, q = lane & 3;
    int r0 = wid*16;
    int rA = r0 + g, rB = r0 + g + 8;

    const float* kg = g_k + (size_t)bh*NT*DH;
    const float* qg = g_q + (size_t)bh*NT*DH;

    if (t == 0) s_smax = 0u;

    for (int i = t; i < ES*DH; i += 256) {
        int m = i >> 6, d = i & 63;
        Ps[m*PS_ST + d] = (m < MM) ? to_tf32(proj[m*64 + d]) : 0.f;
    }
    for (int i = t; i < NT*DH; i += 256) {
        int r = i >> 6, d = i & 63;
        Xs[r*XS_ST + d] = to_tf32(kg[i] * DN);
    }
    if (t < NT) {
        float s = 0.f;
#pragma unroll
        for (int d = 0; d < 64; d++) { float v = kg[t*64+d]*DN; s = fmaf(v,v,s); }
        diag[t] = 0.5f * s;
    }
    __syncthreads();

    // keys
    {
        unsigned a[8][4];
#pragma unroll
        for (int kc = 0; kc < 8; ++kc) {
            a[kc][0] = __float_as_uint(Xs[rA*XS_ST + kc*8 + q]);
            a[kc][1] = __float_as_uint(Xs[rB*XS_ST + kc*8 + q]);
            a[kc][2] = __float_as_uint(Xs[rA*XS_ST + kc*8 + q + 4]);
            a[kc][3] = __float_as_uint(Xs[rB*XS_ST + kc*8 + q + 4]);
        }
        float dgA = diag[rA], dgB = diag[rB];
        float* EA = g_Ek + ((size_t)bh*NT + rA)*ES;
        float* EB = g_Ek + ((size_t)bh*NT + rB)*ES;
        float dmax = -1e30f;

        for (int nc = 0; nc < 34; ++nc) {
            float c0=0.f, c1=0.f, c2=0.f, c3=0.f;
            const float* pb = Ps + (nc*8 + g)*PS_ST + q;
#pragma unroll
            for (int kc = 0; kc < 8; ++kc) {
                unsigned b0 = __float_as_uint(pb[kc*8]);
                unsigned b1 = __float_as_uint(pb[kc*8 + 4]);
                mma_tf32(c0, c1, c2, c3,
                         a[kc][0], a[kc][1], a[kc][2], a[kc][3], b0, b1);
            }
            int n0 = nc*8 + 2*q;
            bool v0 = (n0 < MM), v1 = (n0+1 < MM);
            if (v0) dmax = fmaxf(dmax, fmaxf(c0, c2));
            if (v1) dmax = fmaxf(dmax, fmaxf(c1, c3));
            *(float2*)(EA + n0) = make_float2(__expf(c0 - dgA), __expf(c1 - dgA));
            *(float2*)(EB + n0) = make_float2(__expf(c2 - dgB), __expf(c3 - dgB));
        }
#pragma unroll
        for (int o = 16; o; o >>= 1)
            dmax = fmaxf(dmax, __shfl_xor_sync(0xffffffffu, dmax, o));
        if (lane == 0) atomicMax(&s_smax, enc_f(dmax));
    }
    __syncthreads();
    if (t == 0) atomicMax(&g_kmax, s_smax);

    for (int i = t; i < NT*DH; i += 256) {
        int r = i >> 6, d = i & 63;
        Xs[r*XS_ST + d] = to_tf32(qg[i] * DN);
    }
    if (t < NT) {
        float s = 0.f;
#pragma unroll
        for (int d = 0; d < 64; d++) { float v = qg[t*64+d]*DN; s = fmaf(v,v,s); }
        g_qdg[(size_t)bh*NT + t] = 0.5f * s;
    }
    __syncthreads();

    // queries
    {
        unsigned a[8][4];
#pragma unroll
        for (int kc = 0; kc < 8; ++kc) {
            a[kc][0] = __float_as_uint(Xs[rA*XS_ST + kc*8 + q]);
            a[kc][1] = __float_as_uint(Xs[rB*XS_ST + kc*8 + q]);
            a[kc][2] = __float_as_uint(Xs[rA*XS_ST + kc*8 + q + 4]);
            a[kc][3] = __float_as_uint(Xs[rB*XS_ST + kc*8 + q + 4]);
        }
        float* EA = g_Eq + ((size_t)bh*NT + rA)*ES;
        float* EB = g_Eq + ((size_t)bh*NT + rB)*ES;
        float emxA = 0.f, emxB = 0.f;

        for (int nc = 0; nc < 34; ++nc) {
            float c0=0.f, c1=0.f, c2=0.f, c3=0.f;
            const float* pb = Ps + (nc*8 + g)*PS_ST + q;
#pragma unroll
            for (int kc = 0; kc < 8; ++kc) {
                unsigned b0 = __float_as_uint(pb[kc*8]);
                unsigned b1 = __float_as_uint(pb[kc*8 + 4]);
                mma_tf32(c0, c1, c2, c3,
                         a[kc][0], a[kc][1], a[kc][2], a[kc][3], b0, b1);
            }
            int n0 = nc*8 + 2*q;
            bool v0 = (n0 < MM), v1 = (n0+1 < MM);
            float e0 = __expf(c0), e1 = __expf(c1);
            float e2 = __expf(c2), e3 = __expf(c3);
            if (v0) { emxA = fmaxf(emxA, e0); emxB = fmaxf(emxB, e2); }
            if (v1) { emxA = fmaxf(emxA, e1); emxB = fmaxf(emxB, e3); }
            *(float2*)(EA + n0) = make_float2(e0, e1);
            *(float2*)(EB + n0) = make_float2(e2, e3);
        }
        emxA = fmaxf(emxA, __shfl_xor_sync(0xffffffffu, emxA, 1));
        emxA = fmaxf(emxA, __shfl_xor_sync(0xffffffffu, emxA, 2));
        emxB = fmaxf(emxB, __shfl_xor_sync(0xffffffffu, emxB, 1));
        emxB = fmaxf(emxB, __shfl_xor_sync(0xffffffffu, emxB, 2));
        if (q == 0) {
            g_Emx[(size_t)bh*NT + rA] = emxA;
            g_Emx[(size_t)bh*NT + rB] = emxB;
        }
    }
}

// ---------------- k2b_mma: ctxT = V^T @ Ek + ksum/vsum/csA/kss ----------------
#define EKT_ST 68
#define K2B_SMEM ((ES*EKT_ST + DH*EKT_ST)*4)

__global__ __launch_bounds__(256, 2)
void k2b_mma()
{
    extern __shared__ float sm[];
    float* EkTs = sm;
    float* Vts  = sm + ES*EKT_ST;
    __shared__ float csp[2][64];
    __shared__ float redk[8];

    int bh = blockIdx.x, t = threadIdx.x;
    int wid = t >> 5, lane = t & 31;
    int g = lane >> 2, q = lane & 3;
    int mtile = wid >> 1;
    int w2 = wid & 1;
    int ntb = w2 * 17;

    const float* Ekg = g_Ek + (size_t)bh*NT*ES;
    const float* vg  = g_v  + (size_t)bh*NT*DH;

    float acc[17][4];
#pragma unroll
    for (int j = 0; j < 17; ++j) { acc[j][0]=0.f; acc[j][1]=0.f; acc[j][2]=0.f; acc[j][3]=0.f; }
    float ks0 = 0.f, ks1 = 0.f, vs_r = 0.f;
    int dA = mtile*16 + g, dB = dA + 8;

    for (int c = 0; c < 2; ++c) {
        int n0 = c*64;
        for (int i = t; i < 64*64; i += 256) {
            int n = i >> 6, d = i & 63;
            Vts[d*EKT_ST + n] = vg[(n0+n)*64 + d];
        }
        for (int i = t; i < 64*ES; i += 256) {
            int n = i / ES, m = i - n*ES;
            EkTs[m*EKT_ST + n] = Ekg[(size_t)(n0+n)*ES + m];
        }
        __syncthreads();

        {
            float s = 0.f;
            const float4* r4 = (const float4*)(EkTs + t*EKT_ST);
#pragma unroll
            for (int j = 0; j < 16; ++j) { float4 v = r4[j]; s += (v.x+v.y)+(v.z+v.w); }
            ks0 += s;
            if (t < 16) {
                float s2 = 0.f;
                const float4* r2 = (const float4*)(EkTs + (t+256)*EKT_ST);
#pragma unroll
                for (int j = 0; j < 16; ++j) { float4 v = r2[j]; s2 += (v.x+v.y)+(v.z+v.w); }
                ks1 += s2;
            }
            if (t < 64) {
                float sv = 0.f;
                const float4* rv = (const float4*)(Vts + t*EKT_ST);
#pragma unroll
                for (int j = 0; j < 16; ++j) { float4 v = rv[j]; sv += (v.x+v.y)+(v.z+v.w); }
                vs_r += sv;
            }
        }

#pragma unroll
        for (int ks = 0; ks < 8; ++ks) {
            unsigned a0 = __float_as_uint(Vts[dA*EKT_ST + ks*8 + q]);
            unsigned a1 = __float_as_uint(Vts[dB*EKT_ST + ks*8 + q]);
            unsigned a2 = __float_as_uint(Vts[dA*EKT_ST + ks*8 + q + 4]);
            unsigned a3 = __float_as_uint(Vts[dB*EKT_ST + ks*8 + q + 4]);
#pragma unroll
            for (int j = 0; j < 17; ++j) {
                int mrow = (ntb + j)*8 + g;
                unsigned b0 = __float_as_uint(EkTs[mrow*EKT_ST + ks*8 + q]);
                unsigned b1 = __float_as_uint(EkTs[mrow*EKT_ST + ks*8 + q + 4]);
                mma_tf32(acc[j][0], acc[j][1], acc[j][2], acc[j][3],
                         a0, a1, a2, a3, b0, b1);
            }
        }
        __syncthreads();
    }

    float A = RATIO * __expf(-dec_f(g_kmax));

    {
        float pA = 0.f, pB = 0.f;
#pragma unroll
        for (int j = 0; j < 17; ++j) {
            int m0 = (ntb + j)*8 + 2*q;
            if (m0   < MM) { pA += acc[j][0]; pB += acc[j][2]; }
            if (m0+1 < MM) { pA += acc[j][1]; pB += acc[j][3]; }
        }
        pA += __shfl_xor_sync(0xffffffffu, pA, 1);
        pA += __shfl_xor_sync(0xffffffffu, pA, 2);
        pB += __shfl_xor_sync(0xffffffffu, pB, 1);
        pB += __shfl_xor_sync(0xffffffffu, pB, 2);
        if (q == 0) { csp[w2][dA] = pA; csp[w2][dB] = pB; }
    }

    {
        float kt = (t < MM) ? ks0 : 0.f;
        if (t < 16 && t + 256 < MM) kt += ks1;
#pragma unroll
        for (int o = 16; o; o >>= 1) kt += __shfl_xor_sync(0xffffffffu, kt, o);
        if (lane == 0) redk[wid] = kt;
    }

    float* ctA = g_ctxT + ((size_t)bh*DH + dA)*ES;
    float* ctB = g_ctxT + ((size_t)bh*DH + dB)*ES;
#pragma unroll
    for (int j = 0; j < 17; ++j) {
        int m0 = (ntb + j)*8 + 2*q;
        float e0 = (m0   < MM) ? acc[j][0] : 0.f;
        float e1 = (m0+1 < MM) ? acc[j][1] : 0.f;
        float e2 = (m0   < MM) ? acc[j][2] : 0.f;
        float e3 = (m0+1 < MM) ? acc[j][3] : 0.f;
        *(float2*)(ctA + m0) = make_float2(e0, e1);
        *(float2*)(ctB + m0) = make_float2(e2, e3);
    }
    if (t < MM) g_ksumU[(size_t)bh*MM + t] = ks0;
    if (t < 16 && t + 256 < MM) g_ksumU[(size_t)bh*MM + t + 256] = ks1;
    __syncthreads();
    if (t < DH) {
        g_vsum[(size_t)bh*DH + t] = vs_r;
        g_csA[(size_t)bh*DH + t] =
            fmaf(A, csp[0][t] + csp[1][t], (float)MM * RE * vs_r);
    }
    if (t == 0) {
        float s = 0.f;
#pragma unroll
        for (int w = 0; w < 8; ++w) s += redk[w];
        g_kss[bh] = fmaf(A, s, (float)MM * RE * 128.f);
    }
}

// ---------------- k3b_mma: O = Eq @ ctx_scaled, Tn inline ----------------
#define EQ_ST 137
#define K3B_SMEM ((NT*EQ_ST + DH*EQ_ST)*4)

__global__ __launch_bounds__(512, 1)
void k3b_mma()
{
    extern __shared__ float sm[];
    float* Eqs   = sm;
    float* ctxTs = sm + NT*EQ_ST;
    __shared__ float qd_s[NT], Emx_s[NT], Tn_s[NT], cs_s[DH], vs_s[DH];
    __shared__ float ksm_s[ES];
    __shared__ float sA, skss;

    int bh = blockIdx.x, t = threadIdx.x;
    int wid = t >> 5, lane = t & 31;
    int g = lane >> 2, q = lane & 3;
    int mtile = wid >> 1;
    int dbase = (wid & 1)*32;

    if (t == 0) { sA = RATIO * __expf(-dec_f(g_kmax)); skss = g_kss[bh]; }
    if (t < NT) {
        qd_s[t]  = g_qdg[(size_t)bh*NT + t];
        Emx_s[t] = g_Emx[(size_t)bh*NT + t];
        Tn_s[t]  = 0.f;
    }
    if (t < DH) {
        cs_s[t] = g_csA[(size_t)bh*DH + t];
        vs_s[t] = g_vsum[(size_t)bh*DH + t];
    }
    __syncthreads();
    float A = sA;
    for (int i = t; i < ES; i += 512)
        ksm_s[i] = (i < MM) ? fmaf(A, g_ksumU[(size_t)bh*MM + i], RE*128.f) : 0.f;

    const float* Eqg = g_Eq + (size_t)bh*NT*ES;
    const float* ctg = g_ctxT + (size_t)bh*DH*ES;

    float acc[4][4];
#pragma unroll
    for (int j = 0; j < 4; ++j) { acc[j][0]=0.f; acc[j][1]=0.f; acc[j][2]=0.f; acc[j][3]=0.f; }

    for (int c = 0; c < 2; ++c) {
        int m0 = c*136;
        for (int i = t; i < NT*136; i += 512) {
            int r = i / 136, cc = i - r*136;
            Eqs[r*EQ_ST + cc] = Eqg[(size_t)r*ES + m0 + cc];
        }
        for (int i = t; i < DH*136; i += 512) {
            int d = i / 136, cc = i - d*136;
            int mg = m0 + cc;
            float raw = ctg[(size_t)d*ES + mg];
            ctxTs[d*EQ_ST + cc] = (mg < MM) ? fmaf(A, raw, RE*vs_s[d]) : 0.f;
        }
        __syncthreads();

        for (int j = 0; j < 8; ++j) {
            int n = wid*8 + j;
            const float* er = Eqs + n*EQ_ST;
            float s = 0.f;
            for (int cc = lane; cc < 136; cc += 32)
                s = fmaf(er[cc], ksm_s[m0 + cc], s);
#pragma unroll
            for (int o = 16; o; o >>= 1) s += __shfl_xor_sync(0xffffffffu, s, o);
            if (lane == 0) Tn_s[n] += s;
        }

#pragma unroll
        for (int ks = 0; ks < 17; ++ks) {
            unsigned a0 = __float_as_uint(Eqs[(mtile*16+g)*EQ_ST + ks*8 + q]);
            unsigned a1 = __float_as_uint(Eqs[(mtile*16+g+8)*EQ_ST + ks*8 + q]);
            unsigned a2 = __float_as_uint(Eqs[(mtile*16+g)*EQ_ST + ks*8 + q + 4]);
            unsigned a3 = __float_as_uint(Eqs[(mtile*16+g+8)*EQ_ST + ks*8 + q + 4]);
#pragma unroll
            for (int nt = 0; nt < 4; ++nt) {
                int drow = dbase + nt*8 + g;
                unsigned b0 = __float_as_uint(ctxTs[drow*EQ_ST + ks*8 + q]);
                unsigned b1 = __float_as_uint(ctxTs[drow*EQ_ST + ks*8 + q + 4]);
                mma_tf32(acc[nt][0], acc[nt][1], acc[nt][2], acc[nt][3],
                         a0, a1, a2, a3, b0, b1);
            }
        }
        __syncthreads();
    }

    int rA = mtile*16 + g, rB = rA + 8;
    float rqA = RATIO * __expf(-qd_s[rA]) / Emx_s[rA];
    float rqB = RATIO * __expf(-qd_s[rB]) / Emx_s[rB];
    float kss = skss;
    float invA = 1.0f / fmaf(rqA, Tn_s[rA], RE*kss);
    float invB = 1.0f / fmaf(rqB, Tn_s[rB], RE*kss);
    int b = bh >> 3, h = bh & 7;
    float* oA = g_o + ((size_t)(b*NT + rA))*IN + h*DH;
    float* oB = g_o + ((size_t)(b*NT + rB))*IN + h*DH;
#pragma unroll
    for (int nt = 0; nt < 4; ++nt) {
        int d = dbase + nt*8 + 2*q;
        float2 vA, vB;
        vA.x = fmaf(rqA, acc[nt][0], RE*cs_s[d  ])*invA;
        vA.y = fmaf(rqA, acc[nt][1], RE*cs_s[d+1])*invA;
        vB.x = fmaf(rqB, acc[nt][2], RE*cs_s[d  ])*invB;
        vB.y = fmaf(rqB, acc[nt][3], RE*cs_s[d+1])*invB;
        *(float2*)(oA + d) = vA;
        *(float2*)(oB + d) = vB;
    }
}

// ---------------- k4a_mma ----------------
#define K4A_ST 132
#define K4A_SMEM ((NT*K4A_ST + DH*K4A_ST)*4)

__global__ __launch_bounds__(256, 2)
void k4a_mma(const float* __restrict__ x,
             const float* __restrict__ Wo, const float* __restrict__ bo)
{
    extern __shared__ float sm[];
    float* Os = sm;
    float* Ws = sm + NT*K4A_ST;

    int b = blockIdx.x, t = threadIdx.x;
    int wid = t >> 5, lane = t & 31;
    int g = lane >> 2, q = lane & 3;
    int rA = wid*16 + g, rB = rA + 8;

    float acc[8][4];
#pragma unroll
    for (int j = 0; j < 8; ++j) { acc[j][0]=0.f; acc[j][1]=0.f; acc[j][2]=0.f; acc[j][3]=0.f; }

    const float* ob = g_o + (size_t)b*NT*IN;

    for (int c = 0; c < 4; ++c) {
        int k0 = c*128;
        for (int i = t; i < NT*128; i += 256) {
            int r = i >> 7, kc = i & 127;
            Os[r*K4A_ST + kc] = to_tf32(ob[(size_t)r*IN + k0 + kc]);
        }
        for (int i = t; i < DH*128; i += 256) {
            int k = i >> 6, d = i & 63;
            Ws[d*K4A_ST + k] = to_tf32(Wo[(size_t)(k0+k)*TD + d]);
        }
        __syncthreads();

#pragma unroll
        for (int ks = 0; ks < 16; ++ks) {
            unsigned a0 = __float_as_uint(Os[rA*K4A_ST + ks*8 + q]);
            unsigned a1 = __float_as_uint(Os[rB*K4A_ST + ks*8 + q]);
            unsigned a2 = __float_as_uint(Os[rA*K4A_ST + ks*8 + q + 4]);
            unsigned a3 = __float_as_uint(Os[rB*K4A_ST + ks*8 + q + 4]);
#pragma unroll
            for (int nt = 0; nt < 8; ++nt) {
                int drow = nt*8 + g;
                unsigned b0 = __float_as_uint(Ws[drow*K4A_ST + ks*8 + q]);
                unsigned b1 = __float_as_uint(Ws[drow*K4A_ST + ks*8 + q + 4]);
                mma_tf32(acc[nt][0], acc[nt][1], acc[nt][2], acc[nt][3],
                         a0, a1, a2, a3, b0, b1);
            }
        }
        __syncthreads();
    }

    const float* xb = x + (size_t)b*NT*TD;
    float* tb = g_t + (size_t)b*NT*TD;
#pragma unroll
    for (int nt = 0; nt < 8; ++nt) {
        int d = nt*8 + 2*q;
        float2 bb = *(const float2*)(bo + d);
        float2 xA = *(const float2*)(xb + rA*TD + d);
        float2 xB = *(const float2*)(xb + rB*TD + d);
        *(float2*)(tb + rA*TD + d) =
            make_float2(acc[nt][0] + bb.x + xA.x, acc[nt][1] + bb.y + xA.y);
        *(float2*)(tb + rB*TD + d) =
            make_float2(acc[nt][2] + bb.x + xB.x, acc[nt][3] + bb.y + xB.y);
    }
}

// ---------------- k4b1: LN2 + FF1 (mma) + GELU -> g_ff ----------------
#define FF1_ST 68
#define K4B1_SMEM ((NT*FF1_ST + FH*FF1_ST)*4)

__global__ __launch_bounds__(256, 2)
void k4b1(const float* __restrict__ g2, const float* __restrict__ b2,
          const float* __restrict__ W1, const float* __restrict__ c1)
{
    extern __shared__ float sm[];
    float* hs = sm;
    float* Ws = sm + NT*FF1_ST;

    int b = blockIdx.x, t = threadIdx.x;
    int wid = t >> 5, lane = t & 31;
    int g = lane >> 2, q = lane & 3;
    int rA = wid*16 + g, rB = rA + 8;

    for (int i = t; i < TD*FH; i += 256) {
        int d = i >> 8, j = i & 255;
        Ws[j*FF1_ST + d] = to_tf32(W1[i]);
    }
    if (t < NT) {
        const float* tr = g_t + ((size_t)(b*NT + t))*TD;
        float tv[64];
#pragma unroll
        for (int j = 0; j < 16; ++j) {
            float4 t4 = *(const float4*)(tr + 4*j);
            tv[4*j]=t4.x; tv[4*j+1]=t4.y; tv[4*j+2]=t4.z; tv[4*j+3]=t4.w;
        }
        float mu = 0.f;
#pragma unroll
        for (int d = 0; d < 64; d++) mu += tv[d];
        mu *= (1.f/64.f);
        float var = 0.f;
#pragma unroll
        for (int d = 0; d < 64; d++) { float v = tv[d]-mu; var += v*v; }
        var *= (1.f/64.f);
        float inv = rsqrtf(var + 1e-5f);
#pragma unroll
        for (int d = 0; d < 64; d++)
            hs[t*FF1_ST + d] = to_tf32((tv[d]-mu)*inv*g2[d] + b2[d]);
    }
    __syncthreads();

    unsigned a[8][4];
#pragma unroll
    for (int kc = 0; kc < 8; ++kc) {
        a[kc][0] = __float_as_uint(hs[rA*FF1_ST + kc*8 + q]);
        a[kc][1] = __float_as_uint(hs[rB*FF1_ST + kc*8 + q]);
        a[kc][2] = __float_as_uint(hs[rA*FF1_ST + kc*8 + q + 4]);
        a[kc][3] = __float_as_uint(hs[rB*FF1_ST + kc*8 + q + 4]);
    }

    float* ffb = g_ff + (size_t)b*NT*FH;
    for (int nc = 0; nc < 32; ++nc) {
        float c0=0.f, c1r=0.f, c2=0.f, c3=0.f;
        const float* pb = Ws + (nc*8 + g)*FF1_ST + q;
#pragma unroll
        for (int kc = 0; kc < 8; ++kc) {
            unsigned b0 = __float_as_uint(pb[kc*8]);
            unsigned b1 = __float_as_uint(pb[kc*8 + 4]);
            mma_tf32(c0, c1r, c2, c3,
                     a[kc][0], a[kc][1], a[kc][2], a[kc][3], b0, b1);
        }
        int j0 = nc*8 + 2*q;
        float2 cc = *(const float2*)(c1 + j0);
        float v0 = c0 + cc.x, v1 = c1r + cc.y, v2 = c2 + cc.x, v3 = c3 + cc.y;
        v0 = 0.5f*v0*(1.f + erff(v0*0.70710678f));
        v1 = 0.5f*v1*(1.f + erff(v1*0.70710678f));
        v2 = 0.5f*v2*(1.f + erff(v2*0.70710678f));
        v3 = 0.5f*v3*(1.f + erff(v3*0.70710678f));
        *(float2*)(ffb + (size_t)rA*FH + j0) = make_float2(v0, v1);
        *(float2*)(ffb + (size_t)rB*FH + j0) = make_float2(v2, v3);
    }
}

// ---------------- k4b2: FF2 (mma) + residual + LN3 + pool + head ----------------
#define FF2_ST 132
#define K4B2_SMEM ((NT*FF2_ST + DH*FF2_ST + NT*65)*4)

__global__ __launch_bounds__(256, 1)
void k4b2(const float* __restrict__ x,
          const float* __restrict__ W2, const float* __restrict__ c2,
          const float* __restrict__ g3, const float* __restrict__ b3,
          const float* __restrict__ Wf1, const float* __restrict__ bf1,
          const float* __restrict__ Wf2, const float* __restrict__ bf2,
          float* __restrict__ out)
{
    extern __shared__ float sm[];
    float* As = sm;
    float* Ws = sm + NT*FF2_ST;
    float* rs = Ws + DH*FF2_ST;
    __shared__ float psm[64];
    __shared__ float red[8];

    int b = blockIdx.x, t = threadIdx.x;
    int wid = t >> 5, lane = t & 31;
    int g = lane >> 2, q = lane & 3;
    int rA = wid*16 + g, rB = rA + 8;

    float acc[8][4];
#pragma unroll
    for (int j = 0; j < 8; ++j) { acc[j][0]=0.f; acc[j][1]=0.f; acc[j][2]=0.f; acc[j][3]=0.f; }

    const float* ffb = g_ff + (size_t)b*NT*FH;

    for (int c = 0; c < 2; ++c) {
        int k0 = c*128;
        for (int i = t; i < NT*128; i += 256) {
            int r = i >> 7, kc = i & 127;
            As[r*FF2_ST + kc] = to_tf32(ffb[(size_t)r*FH + k0 + kc]);
        }
        for (int i = t; i < DH*128; i += 256) {
            int kc = i >> 6, d = i & 63;
            Ws[d*FF2_ST + kc] = to_tf32(W2[(size_t)(k0+kc)*TD + d]);
        }
        __syncthreads();

#pragma unroll
        for (int ks = 0; ks < 16; ++ks) {
            unsigned a0 = __float_as_uint(As[rA*FF2_ST + ks*8 + q]);
            unsigned a1 = __float_as_uint(As[rB*FF2_ST + ks*8 + q]);
            unsigned a2 = __float_as_uint(As[rA*FF2_ST + ks*8 + q + 4]);
            unsigned a3 = __float_as_uint(As[rB*FF2_ST + ks*8 + q + 4]);
#pragma unroll
            for (int nt = 0; nt < 8; ++nt) {
                int drow = nt*8 + g;
                unsigned b0 = __float_as_uint(Ws[drow*FF2_ST + ks*8 + q]);
                unsigned b1 = __float_as_uint(Ws[drow*FF2_ST + ks*8 + q + 4]);
                mma_tf32(acc[nt][0], acc[nt][1], acc[nt][2], acc[nt][3],
                         a0, a1, a2, a3, b0, b1);
            }
        }
        __syncthreads();
    }

    const float* xb = x + (size_t)b*NT*TD;
    const float* tb = g_t + (size_t)b*NT*TD;
#pragma unroll
    for (int nt = 0; nt < 8; ++nt) {
        int d = nt*8 + 2*q;
        float2 cc = *(const float2*)(c2 + d);
        float2 tA = *(const float2*)(tb + rA*TD + d);
        float2 tB = *(const float2*)(tb + rB*TD + d);
        float2 xA = *(const float2*)(xb + rA*TD + d);
        float2 xB = *(const float2*)(xb + rB*TD + d);
        rs[rA*65 + d]     = acc[nt][0] + cc.x + tA.x + xA.x;
        rs[rA*65 + d + 1] = acc[nt][1] + cc.y + tA.y + xA.y;
        rs[rB*65 + d]     = acc[nt][2] + cc.x + tB.x + xB.x;
        rs[rB*65 + d + 1] = acc[nt][3] + cc.y + tB.y + xB.y;
    }
    __syncthreads();

    if (t < NT) {
        float* r = &rs[t*65];
        float mu = 0.f;
#pragma unroll
        for (int d = 0; d < 64; d++) mu += r[d];
        mu *= (1.f/64.f);
        float var = 0.f;
#pragma unroll
        for (int d = 0; d < 64; d++) { float v = r[d]-mu; var += v*v; }
        var *= (1.f/64.f);
        float inv = rsqrtf(var + 1e-5f);
#pragma unroll
        for (int d = 0; d < 64; d++)
            r[d] = (r[d]-mu)*inv*g3[d] + b3[d];
    }
    __syncthreads();

    if (t < TD) {
        float s = 0.f;
        for (int nn = 0; nn < NT; ++nn) s += rs[nn*65 + t];
        psm[t] = s * (1.f/128.f);
    }
    __syncthreads();

    float val = 0.f;
    if (t < 128) {
        float s = bf1[t];
        for (int d = 0; d < TD; ++d)
            s = fmaf(psm[d], Wf1[d*128 + t], s);
        s = fmaxf(s, 0.f);
        val = s * Wf2[t];
    }
#pragma unroll
    for (int o = 16; o; o >>= 1)
        val += __shfl_xor_sync(0xffffffffu, val, o);
    if ((t & 31) == 0) red[t >> 5] = val;
    __syncthreads();
    if (t == 0)
        out[b] = red[0] + red[1] + red[2] + red[3] + bf2[0];
}

// ---------------- launch ----------------
extern "C" void kernel_launch(void* const* d_in, const int* in_sizes, int n_in,
                              void* d_out, int out_size) {
    const float* x    = (const float*)d_in[0];
    const float* g1   = (const float*)d_in[1];
    const float* b1   = (const float*)d_in[2];
    const float* Wq   = (const float*)d_in[3];
    const float* bq   = (const float*)d_in[4];
    const float* Wk   = (const float*)d_in[5];
    const float* bk   = (const float*)d_in[6];
    const float* Wv   = (const float*)d_in[7];
    const float* bv   = (const float*)d_in[8];
    const float* Wo   = (const float*)d_in[9];
    const float* bo   = (const float*)d_in[10];
    const float* proj = (const float*)d_in[11];
    const float* g2   = (const float*)d_in[12];
    const float* b2   = (const float*)d_in[13];
    const float* W1   = (const float*)d_in[14];
    const float* c1   = (const float*)d_in[15];
    const float* W2   = (const float*)d_in[16];
    const float* c2   = (const float*)d_in[17];
    const float* g3   = (const float*)d_in[18];
    const float* b3   = (const float*)d_in[19];
    const float* Wf1  = (const float*)d_in[20];
    const float* bf1  = (const float*)d_in[21];
    const float* Wf2  = (const float*)d_in[22];
    const float* bf2  = (const float*)d_in[23];
    float* out = (float*)d_out;

    cudaFuncSetAttribute(k1_mma,  cudaFuncAttributeMaxDynamicSharedMemorySize, K1_SMEM);
    cudaFuncSetAttribute(kfeat,   cudaFuncAttributeMaxDynamicSharedMemorySize, KF_SMEM);
    cudaFuncSetAttribute(k2b_mma, cudaFuncAttributeMaxDynamicSharedMemorySize, K2B_SMEM);
    cudaFuncSetAttribute(k3b_mma, cudaFuncAttributeMaxDynamicSharedMemorySize, K3B_SMEM);
    cudaFuncSetAttribute(k4a_mma, cudaFuncAttributeMaxDynamicSharedMemorySize, K4A_SMEM);
    cudaFuncSetAttribute(k4b1,    cudaFuncAttributeMaxDynamicSharedMemorySize, K4B1_SMEM);
    cudaFuncSetAttribute(k4b2,    cudaFuncAttributeMaxDynamicSharedMemorySize, K4B2_SMEM);

    k_init<<<1, 1>>>();
    k1_mma<<<dim3(BB, 3, 2), 256, K1_SMEM>>>(x, g1, b1, Wq, bq, Wk, bk, Wv, bv);
    kfeat<<<BB*HH, 256, KF_SMEM>>>(proj);
    k2b_mma<<<BB*HH, 256, K2B_SMEM>>>();
    k3b_mma<<<BB*HH, 512, K3B_SMEM>>>();
    k4a_mma<<<BB, 256, K4A_SMEM>>>(x, Wo, bo);
    k4b1<<<BB, 256, K4B1_SMEM>>>(g2, b2, W1, c1);
    k4b2<<<BB, 256, K4B2_SMEM>>>(x, W2, c2, g3, b3, Wf1, bf1, Wf2, bf2, out);
}